// round 10
// baseline (speedup 1.0000x reference)
#include <cuda_runtime.h>

// CASSI forward, one 512-thread CTA per (b,i) row.
//
//   y2[b,i,k]    = sum_l x[b,l,i,k-2l] * phi[i,k-2l]   (0 <= k-2l < N)
//   out[b,l,i,j] = phi[i,j] * y2[b,i,2l+j]
//
// R10: wave-quantization fix. 4096 CTAs at 4 CTAs/SM (512 thr) = 6.92 waves
// (vs 3.46 at TPB=256) -> slot utilization ~99%. Thread t owns y2[k=t]
// (single stream, unpredicated for t>=54) plus tail k=512+t for t<54.
// Epilogue: thread t owns output column j=t; y2_s[2l+t] is stride-1 across
// lanes (conflict-free scalar LDS), stores fully coalesced, zero guards.

#define B_      8
#define L_      28
#define M_      512
#define N_      512
#define STRIDE_ 2
#define NOUT_   (N_ + STRIDE_ * (L_ - 1))   // 566
#define TPB     512
#define TAIL_   (NOUT_ - N_)                // 54

__global__ __launch_bounds__(TPB, 4) void cassi_row_kernel(
    const float* __restrict__ x,
    const float* __restrict__ phi,
    float* __restrict__ out)
{
    __shared__ __align__(16) float phi_s[N_];
    __shared__ __align__(16) float y2_s[NOUT_ + 2];

    const int bm = blockIdx.x;            // (b, i)
    const int b  = bm >> 9;               // / 512
    const int i  = bm & (M_ - 1);
    const int t  = threadIdx.x;

    // ---- phi row i -> smem: 128 threads x float4 ----
    if (t < N_ / 4) {
        const float4* p4 = reinterpret_cast<const float4*>(phi + (size_t)i * N_);
        reinterpret_cast<float4*>(phi_s)[t] = p4[t];
    }
    __syncthreads();

    const size_t band_stride = (size_t)M_ * N_;
    const float* xb = x + (size_t)b * (L_ * M_ * N_) + (size_t)i * N_;

    // ---- accumulate y2[t] (and y2[512+t] for t<54) ----
    float a0 = 0.f, a1 = 0.f;

    if (t >= TAIL_) {
        // hot path: n = t - 2l always in [0, 512) -> zero predication
        const float* xr = xb;
        #pragma unroll
        for (int l = 0; l < L_; ++l) {
            const int n = t - STRIDE_ * l;
            a0 += __ldcs(xr + n) * phi_s[n];
            xr += band_stride;
        }
    } else {
        // edge path (t < 54): k0 = t valid iff l <= t/2; k1 = 512+t valid iff l > t/2
        const float* xr = xb;
        #pragma unroll
        for (int l = 0; l < L_; ++l) {
            unsigned n0 = (unsigned)(t - STRIDE_ * l);
            if (n0 < N_) a0 += __ldcs(xr + n0) * phi_s[n0];
            unsigned n1 = (unsigned)(N_ + t - STRIDE_ * l);
            if (n1 < N_) a1 += __ldcs(xr + n1) * phi_s[n1];
            xr += band_stride;
        }
    }

    y2_s[t] = a0;
    if (t < TAIL_) y2_s[N_ + t] = a1;
    __syncthreads();

    // ---- epilogue: out[b,l,i,t] = phi_s[t] * y2_s[2l + t], no guards ----
    const float pv = phi_s[t];
    float* orow = out + (size_t)b * (L_ * M_ * N_) + (size_t)i * N_ + t;

    #pragma unroll
    for (int l = 0; l < L_; ++l) {
        __stcs(orow, pv * y2_s[STRIDE_ * l + t]);
        orow += band_stride;
    }
}

extern "C" void kernel_launch(void* const* d_in, const int* in_sizes, int n_in,
                              void* d_out, int out_size)
{
    const float* x   = (const float*)d_in[0];
    const float* phi = (const float*)d_in[1];
    float* out       = (float*)d_out;

    cassi_row_kernel<<<B_ * M_, TPB>>>(x, phi, out);
}

// round 11
// speedup vs baseline: 1.1560x; 1.1560x over previous
#include <cuda_runtime.h>
#include <cstdint>

// CASSI forward, cp.async-staged fused kernel.
//
//   y2[b,i,k]    = sum_l x[b,l,i,k-2l] * phi[i,k-2l]   (0 <= k-2l < N)
//   out[b,l,i,j] = phi[i,j] * y2[b,i,2l+j]
//
// R11: decouple load MLP from the register budget. Each CTA (one per (b,i)
// row) streams the 28 band rows x[b,l,i,:] (2KB, 16B-aligned) through a
// 4-deep smem ring with cp.async.cg (LDGSTS: no register residency, L1
// bypass, perfectly coalesced float4). Compute reads staged rows from smem
// (stride-1, conflict-free); per l each thread runs exactly 2 of its 3
// k-streams. Epilogue: conflict-free float2 LDS + coalesced float2 stores.

#define B_      8
#define L_      28
#define M_      512
#define N_      512
#define STRIDE_ 2
#define NOUT_   (N_ + STRIDE_ * (L_ - 1))   // 566
#define TPB     256
#define STAGES  4

__device__ __forceinline__ void cp_async16(uint32_t smem_dst, const void* gptr) {
    asm volatile("cp.async.cg.shared.global [%0], [%1], 16;\n"
                 :: "r"(smem_dst), "l"(gptr));
}

__global__ __launch_bounds__(TPB) void cassi_cpasync_kernel(
    const float* __restrict__ x,
    const float* __restrict__ phi,
    float* __restrict__ out)
{
    __shared__ __align__(16) float phi_s[N_];
    __shared__ __align__(16) float y2_s[NOUT_ + 2];
    __shared__ __align__(16) float xs[STAGES][N_];

    const int bm = blockIdx.x;            // (b, i)
    const int b  = bm >> 9;
    const int i  = bm & (M_ - 1);
    const int t  = threadIdx.x;

    // phi row i -> smem (covered by the first pipeline barrier)
    if (t < N_ / 4) {
        const float4* p4 = reinterpret_cast<const float4*>(phi + (size_t)i * N_);
        reinterpret_cast<float4*>(phi_s)[t] = p4[t];
    }

    const size_t band = (size_t)M_ * N_;
    const float* xb = x + (size_t)b * (L_ * M_ * N_) + (size_t)i * N_;

    const uint32_t xs_smem =
        (uint32_t)__cvta_generic_to_shared(&xs[0][0]);

    // ---- prologue: fill the ring (one commit per stage) ----
    #pragma unroll
    for (int l = 0; l < STAGES; ++l) {
        if (t < N_ / 4) {
            cp_async16(xs_smem + (uint32_t)((l % STAGES) * N_ + t * 4) * 4,
                       xb + (size_t)l * band + t * 4);
        }
        asm volatile("cp.async.commit_group;\n");
    }

    float a0 = 0.f, a1 = 0.f, a2 = 0.f;

    // ---- main pipeline: one wait + compute + one commit per iteration ----
    #pragma unroll
    for (int l = 0; l < L_; ++l) {
        asm volatile("cp.async.wait_group %0;\n" :: "n"(STAGES - 1));
        __syncthreads();                  // stage l visible to all threads

        const float* xr = xs[l % STAGES];

        // stream k1 = t + 256: always valid
        {
            const int n1 = t + TPB - STRIDE_ * l;
            a1 += xr[n1] * phi_s[n1];
        }
        // streams k0 = t (valid iff t >= 2l) and k2 = t + 512 (valid iff t < 2l)
        if (t >= STRIDE_ * l) {
            const int n0 = t - STRIDE_ * l;
            a0 += xr[n0] * phi_s[n0];
        } else {
            const int n2 = t + 2 * TPB - STRIDE_ * l;
            a2 += xr[n2] * phi_s[n2];
        }

        __syncthreads();                  // done reading before refill

        if (l + STAGES < L_) {
            if (t < N_ / 4) {
                cp_async16(xs_smem +
                           (uint32_t)(((l + STAGES) % STAGES) * N_ + t * 4) * 4,
                           xb + (size_t)(l + STAGES) * band + t * 4);
            }
        }
        asm volatile("cp.async.commit_group;\n");   // real or empty group
    }

    // ---- stage y2 ----
    y2_s[t] = a0;
    y2_s[t + TPB] = a1;
    if (t < NOUT_ - 2 * TPB) y2_s[t + 2 * TPB] = a2;   // t < 54
    __syncthreads();

    // ---- epilogue: thread t -> output columns j = {2t, 2t+1};
    //      y2 word offset 2l+2t == float2 index (l+t): conflict-free LDS.64 ----
    const float2 phi_reg = reinterpret_cast<const float2*>(phi_s)[t];
    float* ob = out + (size_t)b * (L_ * M_ * N_) + (size_t)i * N_ + 2 * t;

    #pragma unroll
    for (int l = 0; l < L_; ++l) {
        float2 yv = reinterpret_cast<const float2*>(y2_s)[l + t];
        float2 r;
        r.x = phi_reg.x * yv.x;
        r.y = phi_reg.y * yv.y;
        __stcs(reinterpret_cast<float2*>(ob + (size_t)l * band), r);
    }
}

extern "C" void kernel_launch(void* const* d_in, const int* in_sizes, int n_in,
                              void* d_out, int out_size)
{
    const float* x   = (const float*)d_in[0];
    const float* phi = (const float*)d_in[1];
    float* out       = (float*)d_out;

    cassi_cpasync_kernel<<<B_ * M_, TPB>>>(x, phi, out);
}